// round 17
// baseline (speedup 1.0000x reference)
#include <cuda_runtime.h>
#include <cuda_fp16.h>
#include <math.h>
#include <cstdint>

// Shapes (fixed)
#define Bz 4
#define Sz 1024
#define Ez 1024
#define Hz 16
#define HDz 64
#define DFFz 4096
#define Mz (Bz*Sz)   // 4096 rows of activations
#define MH (Mz/2)    // half-batch chunk (2048 rows)

// ---------------- scratch (device globals; no allocations) ----------------
__device__ __half g_nx  [Mz*Ez];
__device__ __half g_qkv [(size_t)Mz*3*Ez];
__device__ __half g_o   [Mz*Ez];
__device__ float  g_x1  [Mz*Ez];
__device__ __half g_nx2 [Mz*Ez];
__device__ __half g_h1  [(size_t)Mz*DFFz];
__device__ __half g_wqkv[3*Ez*Ez];
__device__ __half g_wo  [Ez*Ez];
__device__ __half g_w1  [(size_t)DFFz*Ez];
__device__ __half g_w2  [(size_t)Ez*DFFz];
__device__ float  g_bqkv[3*Ez];
__device__ uint32_t g_pk[Mz*32];      // packed mask bits: [B*S][S/32]

// ---------------- helpers ----------------
__device__ __forceinline__ float gelu_f(float x) {
    const float c = 0.7978845608028654f; // sqrt(2/pi)
    float u = c * (x + 0.044715f * x * x * x);
    return 0.5f * x * (1.0f + tanhf(u));
}

__device__ __forceinline__ void mma_f16(float* c, const unsigned* a, const unsigned* b) {
    asm volatile(
        "mma.sync.aligned.m16n8k16.row.col.f32.f16.f16.f32 "
        "{%0,%1,%2,%3}, {%4,%5,%6,%7}, {%8,%9}, {%0,%1,%2,%3};\n"
        : "+f"(c[0]), "+f"(c[1]), "+f"(c[2]), "+f"(c[3])
        : "r"(a[0]), "r"(a[1]), "r"(a[2]), "r"(a[3]),
          "r"(b[0]), "r"(b[1]));
}

// f16-accumulate variant: D,C packed as 2x b32 (4 halfs)
__device__ __forceinline__ void mma_f16h(unsigned* c, const unsigned* a, const unsigned* b) {
    asm volatile(
        "mma.sync.aligned.m16n8k16.row.col.f16.f16.f16.f16 "
        "{%0,%1}, {%2,%3,%4,%5}, {%6,%7}, {%0,%1};\n"
        : "+r"(c[0]), "+r"(c[1])
        : "r"(a[0]), "r"(a[1]), "r"(a[2]), "r"(a[3]),
          "r"(b[0]), "r"(b[1]));
}

__device__ __forceinline__ void ldsm_x4(unsigned& r0, unsigned& r1, unsigned& r2, unsigned& r3, unsigned addr) {
    asm volatile("ldmatrix.sync.aligned.m8n8.x4.shared.b16 {%0,%1,%2,%3}, [%4];\n"
                 : "=r"(r0), "=r"(r1), "=r"(r2), "=r"(r3) : "r"(addr));
}
__device__ __forceinline__ void ldsm_x4_t(unsigned& r0, unsigned& r1, unsigned& r2, unsigned& r3, unsigned addr) {
    asm volatile("ldmatrix.sync.aligned.m8n8.x4.trans.shared.b16 {%0,%1,%2,%3}, [%4];\n"
                 : "=r"(r0), "=r"(r1), "=r"(r2), "=r"(r3) : "r"(addr));
}

__device__ __forceinline__ void cp_async16(void* sdst, const void* gsrc) {
    unsigned s = (unsigned)__cvta_generic_to_shared(sdst);
    asm volatile("cp.async.cg.shared.global [%0], [%1], 16;\n" :: "r"(s), "l"(gsrc));
}
__device__ __forceinline__ void cp_commit() {
    asm volatile("cp.async.commit_group;\n" ::);
}
template<int N>
__device__ __forceinline__ void cp_wait() {
    asm volatile("cp.async.wait_group %0;\n" :: "n"(N));
}

// ---------------- fp32 -> fp16 conversion (weights) ----------------
__global__ __launch_bounds__(256) void cvt_h(const float* __restrict__ in,
                                             __half* __restrict__ out, int n4)
{
    int i = blockIdx.x * 256 + threadIdx.x;
    if (i < n4) {
        float4 v = ((const float4*)in)[i];
        __half2 h0 = __floats2half2_rn(v.x, v.y);
        __half2 h1 = __floats2half2_rn(v.z, v.w);
        *(uint2*)(out + (size_t)i * 4) = make_uint2(*(unsigned*)&h0, *(unsigned*)&h1);
    }
}

__global__ __launch_bounds__(256) void bias3_kernel(const float* __restrict__ a,
                                                    const float* __restrict__ b,
                                                    const float* __restrict__ c,
                                                    float* __restrict__ o)
{
    int i = blockIdx.x * 256 + threadIdx.x;
    if (i < Ez) { o[i] = a[i]; o[i + Ez] = b[i]; o[i + 2*Ez] = c[i]; }
}

// ---------------- pack mask to bits (1 = keep score, 0 = use -0.01) ----------------
__global__ __launch_bounds__(256) void pack_mask(const int* __restrict__ mask,
                                                 uint32_t* __restrict__ pk)
{
    int row = blockIdx.x;                  // b*S + q
    int lane = threadIdx.x & 31, w = threadIdx.x >> 5;   // 8 warps
    const int* mrow = mask + (size_t)row * Sz;
    #pragma unroll
    for (int it = 0; it < 4; it++) {
        int word = it * 8 + w;
        int v = mrow[word * 32 + lane];
        unsigned bits = __ballot_sync(0xffffffffu, v != 0);
        if (lane == 0) pk[row * 32 + word] = bits;
    }
}

// ---------------- LayerNorm (ddof=1, eps added to std); half output ----------------
__global__ __launch_bounds__(256) void ln_kernel(const float* __restrict__ x,
                                                 const float* __restrict__ g,
                                                 const float* __restrict__ be,
                                                 __half* __restrict__ y)
{
    __shared__ float red[32];
    int row = blockIdx.x;
    int tid = threadIdx.x;
    const float4* xr = (const float4*)(x + (size_t)row * Ez);
    float4 v = xr[tid];

    float s = v.x + v.y + v.z + v.w;
    #pragma unroll
    for (int o = 16; o > 0; o >>= 1) s += __shfl_xor_sync(0xffffffffu, s, o);
    if ((tid & 31) == 0) red[tid >> 5] = s;
    __syncthreads();
    float t = (tid < 8) ? red[tid] : 0.0f;
    if (tid < 32) {
        #pragma unroll
        for (int o = 4; o > 0; o >>= 1) t += __shfl_xor_sync(0xffffffffu, t, o);
        if (tid == 0) red[0] = t;
    }
    __syncthreads();
    float mean = red[0] * (1.0f / Ez);
    __syncthreads();

    float dx = v.x - mean, dy = v.y - mean, dz = v.z - mean, dw = v.w - mean;
    float sq = dx*dx + dy*dy + dz*dz + dw*dw;
    #pragma unroll
    for (int o = 16; o > 0; o >>= 1) sq += __shfl_xor_sync(0xffffffffu, sq, o);
    if ((tid & 31) == 0) red[tid >> 5] = sq;
    __syncthreads();
    float t2 = (tid < 8) ? red[tid] : 0.0f;
    if (tid < 32) {
        #pragma unroll
        for (int o = 4; o > 0; o >>= 1) t2 += __shfl_xor_sync(0xffffffffu, t2, o);
        if (tid == 0) red[0] = t2;
    }
    __syncthreads();
    float var = red[0] * (1.0f / (Ez - 1));
    float inv = 1.0f / (sqrtf(var) + 1e-8f);

    float4 gg = ((const float4*)g)[tid];
    float4 bb = ((const float4*)be)[tid];
    __half2 h0 = __floats2half2_rn(gg.x * dx * inv + bb.x, gg.y * dy * inv + bb.y);
    __half2 h1 = __floats2half2_rn(gg.z * dz * inv + bb.z, gg.w * dw * inv + bb.w);
    *(uint2*)(y + (size_t)row * Ez + tid * 4) = make_uint2(*(unsigned*)&h0, *(unsigned*)&h1);
}

// ---------------- FP16 tensor-core GEMM, cp.async 3-stage, ldmatrix, 2 CTA/SM ----------------
// Inner accumulation in f16 per 64-K chunk (possible 2x HMMA rate), folded into fp32 masters.
#define BM 128
#define BNt 128
#define BKh 64
#define STH 72      // half stride: 36 words == 4 mod 32 -> conflict-free
#define STAGES 3

#define GEMM_SMEM (STAGES*(BM+BNt)*STH*2)

template<int ACT, bool RES, bool HOUT, bool QSC>
__global__ __launch_bounds__(256, 2) void gemm_f16(const __half* __restrict__ A,
                                                   const __half* __restrict__ Bw,
                                                   const float* __restrict__ bias,
                                                   const float* __restrict__ res,
                                                   float* __restrict__ Cf,
                                                   __half* __restrict__ Ch,
                                                   int M, int N, int K)
{
    extern __shared__ __half smem[];
    __half* As = smem;                          // [STAGES][BM][STH]
    __half* Bs = smem + STAGES * BM * STH;      // [STAGES][BNt][STH]

    const int tid  = threadIdx.x;
    const int warp = tid >> 5, lane = tid & 31;
    const int wm = warp >> 1, wn = warp & 1;    // 4 x 2, warp tile 32x64
    const int qr = lane >> 2, qt = lane & 3;
    const int lane_r  = lane & 15;
    const int lane_c8 = (lane >> 4) * 8;
    const int rowBase = blockIdx.y * BM;
    const int colBase = blockIdx.x * BNt;

    float acc[2][8][4];
    #pragma unroll
    for (int mi = 0; mi < 2; mi++)
        #pragma unroll
        for (int ni = 0; ni < 8; ni++)
            #pragma unroll
            for (int r = 0; r < 4; r++) acc[mi][ni][r] = 0.0f;

    auto prefetch = [&](int k0, int buf) {
        __half* as = As + buf * BM * STH;
        __half* bs = Bs + buf * BNt * STH;
        #pragma unroll
        for (int l = 0; l < 4; l++) {
            int idx = l * 256 + tid;
            int r = idx >> 3, c = (idx & 7) * 8;
            cp_async16(as + r * STH + c, A + (size_t)(rowBase + r) * K + k0 + c);
        }
        #pragma unroll
        for (int l = 0; l < 4; l++) {
            int idx = l * 256 + tid;
            int r = idx >> 3, c = (idx & 7) * 8;
            cp_async16(bs + r * STH + c, Bw + (size_t)(colBase + r) * K + k0 + c);
        }
    };

    const int T = K / BKh;
    #pragma unroll
    for (int s = 0; s < STAGES - 1; s++) { prefetch(s * BKh, s); cp_commit(); }

    for (int t = 0; t < T; t++) {
        cp_wait<STAGES - 2>();
        __syncthreads();
        if (t + STAGES - 1 < T) prefetch((t + STAGES - 1) * BKh, (t + STAGES - 1) % STAGES);
        cp_commit();

        unsigned a_base = (unsigned)__cvta_generic_to_shared(
            As + (t % STAGES) * BM * STH + (wm * 32 + lane_r) * STH + lane_c8);
        unsigned b_base = (unsigned)__cvta_generic_to_shared(
            Bs + (t % STAGES) * BNt * STH + (wn * 64 + lane_r) * STH + lane_c8);

        // two N-halves: f16 accumulators live only within a half (16 regs)
        #pragma unroll
        for (int hn = 0; hn < 2; hn++) {
            unsigned hacc[2][4][2];
            #pragma unroll
            for (int mi = 0; mi < 2; mi++)
                #pragma unroll
                for (int j = 0; j < 4; j++) { hacc[mi][j][0] = 0u; hacc[mi][j][1] = 0u; }

            #pragma unroll
            for (int kk = 0; kk < BKh; kk += 16) {
                unsigned af[2][4];
                #pragma unroll
                for (int mi = 0; mi < 2; mi++)
                    ldsm_x4(af[mi][0], af[mi][1], af[mi][2], af[mi][3],
                            a_base + (mi * 16 * STH + kk) * 2);
                #pragma unroll
                for (int nt = 0; nt < 2; nt++) {
                    int ntg = hn * 2 + nt;
                    unsigned r0, r1, r2, r3;
                    ldsm_x4(r0, r1, r2, r3, b_base + (ntg * 16 * STH + kk) * 2);
                    unsigned b0f[2] = {r0, r2}, b1f[2] = {r1, r3};
                    #pragma unroll
                    for (int mi = 0; mi < 2; mi++) {
                        mma_f16h(hacc[mi][nt*2],   af[mi], b0f);
                        mma_f16h(hacc[mi][nt*2+1], af[mi], b1f);
                    }
                }
            }

            // fold f16 chunk sums into fp32 masters
            #pragma unroll
            for (int mi = 0; mi < 2; mi++)
                #pragma unroll
                for (int j = 0; j < 4; j++) {
                    int ni = hn * 4 + j;
                    float2 f0 = __half22float2(*(__half2*)&hacc[mi][j][0]);
                    float2 f1 = __half22float2(*(__half2*)&hacc[mi][j][1]);
                    acc[mi][ni][0] += f0.x; acc[mi][ni][1] += f0.y;
                    acc[mi][ni][2] += f1.x; acc[mi][ni][3] += f1.y;
                }
        }
    }

    // epilogue
    const float sc = (QSC && colBase < Ez) ? 0.125f : 1.0f;
    #pragma unroll
    for (int mi = 0; mi < 2; mi++) {
        int r0 = rowBase + wm * 32 + mi * 16 + qr;
        #pragma unroll
        for (int ni = 0; ni < 8; ni++) {
            int cc = colBase + wn * 64 + ni * 8 + qt * 2;
            float b0 = bias[cc], b1 = bias[cc + 1];
            float v0 = acc[mi][ni][0] + b0;
            float v1 = acc[mi][ni][1] + b1;
            float v2 = acc[mi][ni][2] + b0;
            float v3 = acc[mi][ni][3] + b1;
            if (RES) {
                v0 += res[(size_t)r0 * N + cc];
                v1 += res[(size_t)r0 * N + cc + 1];
                v2 += res[(size_t)(r0 + 8) * N + cc];
                v3 += res[(size_t)(r0 + 8) * N + cc + 1];
            }
            if (ACT == 1) { v0 = gelu_f(v0); v1 = gelu_f(v1); v2 = gelu_f(v2); v3 = gelu_f(v3); }
            if (QSC) { v0 *= sc; v1 *= sc; v2 *= sc; v3 *= sc; }
            if (HOUT) {
                __half2 h01 = __floats2half2_rn(v0, v1);
                __half2 h23 = __floats2half2_rn(v2, v3);
                *(unsigned*)(Ch + (size_t)r0 * N + cc)       = *(unsigned*)&h01;
                *(unsigned*)(Ch + (size_t)(r0 + 8) * N + cc) = *(unsigned*)&h23;
            } else {
                *(float2*)(Cf + (size_t)r0 * N + cc)       = make_float2(v0, v1);
                *(float2*)(Cf + (size_t)(r0 + 8) * N + cc) = make_float2(v2, v3);
            }
        }
    }
}

// ---------------- FP16 fused attention: 128-q rows/CTA, register-resident P ----------------
// QKV/O are BASE pointers; b0 selects the batch range (global row index b*Sz+q).
#define AST 72
#define QKVS (3*Ez)
#define ATTN_SMEM ((128*AST + 2*64*AST + 2*64*AST) * 2)

__global__ __launch_bounds__(256, 2) void attn_mma(const __half* __restrict__ QKV,
                                                   const uint32_t* __restrict__ pk,
                                                   __half* __restrict__ O, int b0)
{
    extern __shared__ __half smh[];
    __half* Qs = smh;                   // [128][72]
    __half* Ks = smh + 128*AST;         // [2][64][72]
    __half* Vs = smh + 128*AST + 2*64*AST;

    const int qt_ = blockIdx.x, h = blockIdx.y, b = blockIdx.z + b0;
    const int q0 = qt_ * 128;
    const int tid = threadIdx.x;
    const int warp = tid >> 5, lane = tid & 31;
    const int qr = lane >> 2, qt = lane & 3;
    const int lane_r  = lane & 15;
    const int lane_c8 = (lane >> 4) * 8;

    const __half* Qg = QKV + h * HDz;
    const __half* Kg = QKV + Ez + h * HDz;
    const __half* Vg = QKV + 2 * Ez + h * HDz;

    #pragma unroll
    for (int l = 0; l < 4; l++) {
        int idx = l * 256 + tid;
        int r = idx >> 3, c = (idx & 7) * 8;
        cp_async16(Qs + r * AST + c, Qg + (size_t)(b*Sz + q0 + r) * QKVS + c);
    }
    cp_commit();

    auto prefetch = [&](int t, int buf) {
        int k0 = t * 64;
        #pragma unroll
        for (int l = 0; l < 2; l++) {
            int idx = l * 256 + tid;
            int r = idx >> 3, c = (idx & 7) * 8;
            cp_async16(Ks + buf*64*AST + r*AST + c, Kg + (size_t)(b*Sz + k0 + r) * QKVS + c);
            cp_async16(Vs + buf*64*AST + r*AST + c, Vg + (size_t)(b*Sz + k0 + r) * QKVS + c);
        }
    };

    prefetch(0, 0); cp_commit();

    cp_wait<1>();
    __syncthreads();
    unsigned qf[4][4];
    {
        unsigned qa = (unsigned)__cvta_generic_to_shared(Qs + (warp*16 + lane_r)*AST + lane_c8);
        #pragma unroll
        for (int k4 = 0; k4 < 4; k4++)
            ldsm_x4(qf[k4][0], qf[k4][1], qf[k4][2], qf[k4][3], qa + k4 * 32);
    }

    float acc[8][4];
    #pragma unroll
    for (int j = 0; j < 8; j++)
        #pragma unroll
        for (int r = 0; r < 4; r++) acc[j][r] = 0.0f;
    float rs0 = 0.f, rs1 = 0.f;
    const float EM = 0.99004983374916805f;   // exp(-0.01)

    const uint32_t* pk0 = pk + (size_t)(b*Sz + q0 + warp*16 + qr) * 32;
    const uint32_t* pk1 = pk0 + 8 * 32;

    for (int t = 0; t < Sz/64; t++) {
        int buf = t & 1;
        cp_wait<0>();
        __syncthreads();
        if (t + 1 < Sz/64) prefetch(t + 1, buf ^ 1);
        cp_commit();

        uint2 mw0 = *(const uint2*)(pk0 + t * 2);
        uint2 mw1 = *(const uint2*)(pk1 + t * 2);

        unsigned kb = (unsigned)__cvta_generic_to_shared(
            Ks + buf*64*AST + lane_r*AST + lane_c8);
        float scs[8][4];
        #pragma unroll
        for (int j = 0; j < 8; j++)
            #pragma unroll
            for (int r = 0; r < 4; r++) scs[j][r] = 0.0f;

        #pragma unroll
        for (int k4 = 0; k4 < 4; k4++) {
            #pragma unroll
            for (int nt = 0; nt < 4; nt++) {
                unsigned r0, r1, r2, r3;
                ldsm_x4(r0, r1, r2, r3, kb + (nt * 16 * AST + k4 * 16) * 2);
                unsigned b0f[2] = {r0, r2}, b1f[2] = {r1, r3};
                mma_f16(scs[nt*2],   qf[k4], b0f);
                mma_f16(scs[nt*2+1], qf[k4], b1f);
            }
        }

        #pragma unroll
        for (int j = 0; j < 8; j++) {
            int cc = j * 8 + 2 * qt;
            unsigned w0 = (j < 4) ? mw0.x : mw0.y;
            unsigned w1 = (j < 4) ? mw1.x : mw1.y;
            int sh = cc & 31;
            float p00 = ((w0 >> sh) & 1u)       ? __expf(scs[j][0]) : EM;
            float p01 = ((w0 >> (sh+1)) & 1u)   ? __expf(scs[j][1]) : EM;
            float p10 = ((w1 >> sh) & 1u)       ? __expf(scs[j][2]) : EM;
            float p11 = ((w1 >> (sh+1)) & 1u)   ? __expf(scs[j][3]) : EM;
            rs0 += p00 + p01;
            rs1 += p10 + p11;
            scs[j][0] = p00; scs[j][1] = p01; scs[j][2] = p10; scs[j][3] = p11;
        }

        unsigned vb = (unsigned)__cvta_generic_to_shared(
            Vs + buf*64*AST + lane_r*AST + lane_c8);
        #pragma unroll
        for (int j2 = 0; j2 < 4; j2++) {
            unsigned af[4];
            __half2 a0 = __floats2half2_rn(scs[2*j2][0],   scs[2*j2][1]);
            __half2 a1 = __floats2half2_rn(scs[2*j2][2],   scs[2*j2][3]);
            __half2 a2 = __floats2half2_rn(scs[2*j2+1][0], scs[2*j2+1][1]);
            __half2 a3 = __floats2half2_rn(scs[2*j2+1][2], scs[2*j2+1][3]);
            af[0] = *(unsigned*)&a0; af[1] = *(unsigned*)&a1;
            af[2] = *(unsigned*)&a2; af[3] = *(unsigned*)&a3;
            #pragma unroll
            for (int nt = 0; nt < 4; nt++) {
                unsigned r0, r1, r2, r3;
                ldsm_x4_t(r0, r1, r2, r3, vb + (j2 * 16 * AST + nt * 16) * 2);
                unsigned b0f[2] = {r0, r1}, b1f[2] = {r2, r3};
                mma_f16(acc[nt*2],   af, b0f);
                mma_f16(acc[nt*2+1], af, b1f);
            }
        }
    }

    rs0 += __shfl_xor_sync(0xffffffffu, rs0, 1);
    rs0 += __shfl_xor_sync(0xffffffffu, rs0, 2);
    rs1 += __shfl_xor_sync(0xffffffffu, rs1, 1);
    rs1 += __shfl_xor_sync(0xffffffffu, rs1, 2);
    float inv0 = 1.0f / rs0;
    float inv1 = 1.0f / rs1;

    const size_t row0 = (size_t)(b*Sz + q0 + warp*16 + qr);
    #pragma unroll
    for (int j = 0; j < 8; j++) {
        int cc = h*HDz + j*8 + 2*qt;
        __half2 h0 = __floats2half2_rn(acc[j][0] * inv0, acc[j][1] * inv0);
        __half2 h1 = __floats2half2_rn(acc[j][2] * inv1, acc[j][3] * inv1);
        *(unsigned*)(O + row0 * Ez + cc)       = *(unsigned*)&h0;
        *(unsigned*)(O + (row0 + 8) * Ez + cc) = *(unsigned*)&h1;
    }
}

// ---------------- launch ----------------
extern "C" void kernel_launch(void* const* d_in, const int* in_sizes, int n_in,
                              void* d_out, int out_size)
{
    const float* x   = (const float*)d_in[0];
    const int*   msk = (const int*)  d_in[1];
    const float* Wq  = (const float*)d_in[2];
    const float* bq  = (const float*)d_in[3];
    const float* Wk  = (const float*)d_in[4];
    const float* bk  = (const float*)d_in[5];
    const float* Wv  = (const float*)d_in[6];
    const float* bv  = (const float*)d_in[7];
    const float* Wo  = (const float*)d_in[8];
    const float* bo  = (const float*)d_in[9];
    const float* W1  = (const float*)d_in[10];
    const float* b1  = (const float*)d_in[11];
    const float* W2  = (const float*)d_in[12];
    const float* b2  = (const float*)d_in[13];
    const float* g1  = (const float*)d_in[14];
    const float* be1 = (const float*)d_in[15];
    const float* g2  = (const float*)d_in[16];
    const float* be2 = (const float*)d_in[17];
    float* out = (float*)d_out;

    __half *nx, *qkv, *o, *nx2, *h1, *wqkv, *wo, *w1, *w2;
    float *x1, *bqkv;
    uint32_t* pk;
    cudaGetSymbolAddress((void**)&nx,   g_nx);
    cudaGetSymbolAddress((void**)&qkv,  g_qkv);
    cudaGetSymbolAddress((void**)&o,    g_o);
    cudaGetSymbolAddress((void**)&x1,   g_x1);
    cudaGetSymbolAddress((void**)&nx2,  g_nx2);
    cudaGetSymbolAddress((void**)&h1,   g_h1);
    cudaGetSymbolAddress((void**)&wqkv, g_wqkv);
    cudaGetSymbolAddress((void**)&wo,   g_wo);
    cudaGetSymbolAddress((void**)&w1,   g_w1);
    cudaGetSymbolAddress((void**)&w2,   g_w2);
    cudaGetSymbolAddress((void**)&bqkv, g_bqkv);
    cudaGetSymbolAddress((void**)&pk,   g_pk);

    static cudaStream_t s1 = nullptr, s2 = nullptr, sB = nullptr;
    static cudaEvent_t ev0 = nullptr, ev1 = nullptr, ev2 = nullptr;
    static cudaEvent_t evQB = nullptr, evB = nullptr;
    static bool attr_done = false;
    if (!attr_done) {
        cudaFuncSetAttribute((const void*)gemm_f16<0,false,true,true>,   cudaFuncAttributeMaxDynamicSharedMemorySize, GEMM_SMEM);
        cudaFuncSetAttribute((const void*)gemm_f16<0,true,false,false>,  cudaFuncAttributeMaxDynamicSharedMemorySize, GEMM_SMEM);
        cudaFuncSetAttribute((const void*)gemm_f16<1,false,true,false>,  cudaFuncAttributeMaxDynamicSharedMemorySize, GEMM_SMEM);
        cudaFuncSetAttribute((const void*)attn_mma, cudaFuncAttributeMaxDynamicSharedMemorySize, ATTN_SMEM);
        cudaStreamCreateWithFlags(&s1, cudaStreamNonBlocking);
        cudaStreamCreateWithFlags(&s2, cudaStreamNonBlocking);
        cudaStreamCreateWithFlags(&sB, cudaStreamNonBlocking);
        cudaEventCreateWithFlags(&ev0,  cudaEventDisableTiming);
        cudaEventCreateWithFlags(&ev1,  cudaEventDisableTiming);
        cudaEventCreateWithFlags(&ev2,  cudaEventDisableTiming);
        cudaEventCreateWithFlags(&evQB, cudaEventDisableTiming);
        cudaEventCreateWithFlags(&evB,  cudaEventDisableTiming);
        attr_done = true;
    }

    const int nE4 = Ez*Ez/4;
    const int nF4 = DFFz*Ez/4;

    cudaEventRecord(ev0, 0);

    // s1: pack mask + convert Wo/W1/W2 (overlaps LN1/QKV GEMMs)
    cudaStreamWaitEvent(s1, ev0, 0);
    pack_mask<<<Mz, 256, 0, s1>>>(msk, pk);
    cvt_h<<<(nE4+255)/256, 256, 0, s1>>>(Wo, wo, nE4);
    cvt_h<<<(nF4+255)/256, 256, 0, s1>>>(W1, w1, nF4);
    cvt_h<<<(nF4+255)/256, 256, 0, s1>>>(W2, w2, nF4);
    cudaEventRecord(ev1, s1);

    // s2: QKV weights + bias (overlaps LN1)
    cudaStreamWaitEvent(s2, ev0, 0);
    cvt_h<<<(nE4+255)/256, 256, 0, s2>>>(Wq, wqkv,           nE4);
    cvt_h<<<(nE4+255)/256, 256, 0, s2>>>(Wk, wqkv + Ez*Ez,   nE4);
    cvt_h<<<(nE4+255)/256, 256, 0, s2>>>(Wv, wqkv + 2*Ez*Ez, nE4);
    bias3_kernel<<<4, 256, 0, s2>>>(bq, bk, bv, bqkv);
    cudaEventRecord(ev2, s2);

    // chunk geometry (half batches: rows [0,2048) and [2048,4096))
    dim3 gQKVh(3*Ez/BNt, MH/BM);   // (24, 16)
    dim3 gEh(Ez/BNt,     MH/BM);   // (8, 16)
    dim3 gFh(DFFz/BNt,   MH/BM);   // (32, 16)
    const size_t offE = (size_t)MH * Ez;
    const size_t offQ = (size_t)MH * 3*Ez;
    const size_t offF = (size_t)MH * DFFz;

    // main: LN1 full, then QKV_A, QKV_B serialized (B's QKV overlaps A's attention)
    ln_kernel<<<Mz, 256>>>(x, g1, be1, nx);
    cudaStreamWaitEvent(0, ev2, 0);
    gemm_f16<0,false,true,true><<<gQKVh, 256, GEMM_SMEM>>>(nx, wqkv, bqkv, nullptr, nullptr, qkv, MH, 3*Ez, Ez);
    gemm_f16<0,false,true,true><<<gQKVh, 256, GEMM_SMEM>>>(nx + offE, wqkv, bqkv, nullptr, nullptr, qkv + offQ, MH, 3*Ez, Ez);
    cudaEventRecord(evQB, 0);

    // chain B on side stream sB (attn gets BASE pointers; b0=2 selects batches 2,3)
    cudaStreamWaitEvent(sB, evQB, 0);
    cudaStreamWaitEvent(sB, ev1, 0);
    attn_mma<<<dim3(Sz/128, Hz, 2), 256, ATTN_SMEM, sB>>>(qkv, pk, o, 2);
    gemm_f16<0,true,false,false><<<gEh, 256, GEMM_SMEM, sB>>>(o + offE, wo, bo, x + offE, x1 + offE, nullptr, MH, Ez, Ez);
    ln_kernel<<<MH, 256, 0, sB>>>(x1 + offE, g2, be2, nx2 + offE);
    gemm_f16<1,false,true,false><<<gFh, 256, GEMM_SMEM, sB>>>(nx2 + offE, w1, b1, nullptr, nullptr, h1 + offF, MH, DFFz, Ez);
    gemm_f16<0,true,false,false><<<gEh, 256, GEMM_SMEM, sB>>>(h1 + offF, w2, b2, x1 + offE, out + offE, nullptr, MH, Ez, DFFz);
    cudaEventRecord(evB, sB);

    // chain A on main
    cudaStreamWaitEvent(0, ev1, 0);
    attn_mma<<<dim3(Sz/128, Hz, 2), 256, ATTN_SMEM>>>(qkv, pk, o, 0);
    gemm_f16<0,true,false,false><<<gEh, 256, GEMM_SMEM>>>(o, wo, bo, x, x1, nullptr, MH, Ez, Ez);
    ln_kernel<<<MH, 256>>>(x1, g2, be2, nx2);
    gemm_f16<1,false,true,false><<<gFh, 256, GEMM_SMEM>>>(nx2, w1, b1, nullptr, nullptr, h1, MH, DFFz, Ez);
    gemm_f16<0,true,false,false><<<gEh, 256, GEMM_SMEM>>>(h1, w2, b2, x1, out, nullptr, MH, Ez, DFFz);

    // join chain B
    cudaStreamWaitEvent(0, evB, 0);
}